// round 12
// baseline (speedup 1.0000x reference)
#include <cuda_runtime.h>
#include <math.h>

#define NB   64
#define TE   512
#define KSZ  128
#define VSZ  128
#define HD   512
#define TD   99
#define VOC  32000
#define MROWS 6336
#define MPAD  6400
#define NBLK  128
#define G1   2048
#define G2   512
#define KREC 640            // serial K for both gate GEMMs

// ---------------- static device scratch ----------------
__device__ float g_embs[(size_t)MPAD * HD];          // 13.1 MB
__device__ float g_pre1[(size_t)MPAD * G1];          // 52.4 MB (emb part of gates1)
__device__ float g_A[(size_t)MPAD * 256];            // [t*64+n][h2|ctx]
__device__ float g_h1[2][NB * HD];
__device__ float g_c1[NB * HD];
__device__ float g_h2[2][NB * KSZ];
__device__ float g_c2[NB * KSZ];
__device__ float g_ctx[NB * VSZ];
__device__ float g_b1[G1];
__device__ float g_b2[G2];
__device__ volatile int g_flags[NBLK];

__device__ __forceinline__ float sigf(float x) { return 1.f / (1.f + expf(-x)); }

__device__ __forceinline__ float tf32r(float x) {
    asm("cvt.rna.tf32.f32 %0, %0;" : "+f"(x));
    return x;
}

// packed dual-fp32 FMA (sm_100+)
#define FMA2(d, a, b) asm("fma.rn.f32x2 %0, %1, %2, %0;" : "+l"(d) : "l"(a), "l"(b))

__device__ __forceinline__ float f2lo(unsigned long long u) {
    return __uint_as_float((unsigned)u);
}
__device__ __forceinline__ float f2hi(unsigned long long u) {
    return __uint_as_float((unsigned)(u >> 32));
}

// grid-wide barrier: flag-array, no central atomic.
// Each block release-stores its own flag = gen; threads 0..127 each poll one flag.
__device__ __forceinline__ void gbar(int gen) {
    __syncthreads();
    if (threadIdx.x == 0) {
        __threadfence();
        g_flags[blockIdx.x] = gen;
    }
    if (threadIdx.x < NBLK) {
        while (g_flags[threadIdx.x] < gen) { }
        __threadfence();
    }
    __syncthreads();
}

// ---------------- setup: states, biases, embedding gather, flag reset ------------
__global__ void setup_kernel(const float* __restrict__ bih1, const float* __restrict__ bhh1,
                             const float* __restrict__ bih2, const float* __restrict__ bhh2,
                             const float* __restrict__ embedding, const int* __restrict__ text)
{
    const long S_FLG = NBLK;
    const long S_B1 = G1, S_B2 = G2;
    const long S_H1 = 2L * NB * HD, S_C1 = NB * HD;
    const long S_H2 = 2L * NB * KSZ, S_C2 = NB * KSZ, S_CTX = NB * VSZ;
    const long S_EMB = (long)MPAD * HD;
    const long S_APAD = (long)(MPAD - MROWS) * 256;
    const long total = S_FLG + S_B1 + S_B2 + S_H1 + S_C1 + S_H2 + S_C2 + S_CTX + S_EMB + S_APAD;
    const long stride = (long)gridDim.x * blockDim.x;

    for (long idx = (long)blockIdx.x * blockDim.x + threadIdx.x; idx < total; idx += stride) {
        long i = idx;
        if (i < S_FLG) { g_flags[i] = 0; continue; } i -= S_FLG;
        if (i < S_B1) { g_b1[i] = bih1[i] + bhh1[i]; continue; } i -= S_B1;
        if (i < S_B2) { g_b2[i] = bih2[i] + bhh2[i]; continue; } i -= S_B2;
        if (i < S_H1) { ((float*)g_h1)[i] = 0.f; continue; } i -= S_H1;
        if (i < S_C1) { g_c1[i] = 0.f; continue; } i -= S_C1;
        if (i < S_H2) { ((float*)g_h2)[i] = 0.f; continue; } i -= S_H2;
        if (i < S_C2) { g_c2[i] = 0.f; continue; } i -= S_C2;
        if (i < S_CTX){ g_ctx[i] = 0.f; continue; } i -= S_CTX;
        if (i < S_EMB) {
            long row = i / HD; int d = (int)(i % HD);
            if (row < MROWS) {
                int t = (int)(row >> 6), n = (int)(row & 63);
                int tok = text[n * 100 + t];
                g_embs[i] = embedding[(size_t)tok * HD + d];
            } else g_embs[i] = 0.f;
            continue;
        }
        i -= S_EMB;
        g_A[(size_t)MROWS * 256 + i] = 0.f;
    }
}

// ---------------- tf32 GEMM: g_pre1[6400,2048] = g_embs[6400,512] @ Wih1[:, :512]^T --
__global__ __launch_bounds__(256) void pre_gemm(const float* __restrict__ B)
{
    __shared__ float As[128][36];
    __shared__ float Bs[128][36];
    const int tid = threadIdx.x;
    const int lane = tid & 31;
    const int warp = tid >> 5;
    const int wm = warp & 1;
    const int wn = warp >> 1;
    const int mBase = blockIdx.y * 128;
    const int nBase = blockIdx.x * 128;

    float acc[4][4][4];
#pragma unroll
    for (int i = 0; i < 4; i++)
#pragma unroll
        for (int j = 0; j < 4; j++)
#pragma unroll
            for (int q = 0; q < 4; q++) acc[i][j][q] = 0.f;

    const int lr = tid >> 3;
    const int kq = (tid & 7) * 4;

    for (int k0 = 0; k0 < 512; k0 += 32) {
#pragma unroll
        for (int p = 0; p < 4; p++) {
            int row = lr + p * 32;
            float4 va = *(const float4*)(g_embs + (size_t)(mBase + row) * 512 + k0 + kq);
            float4 vb = *(const float4*)(B + (size_t)(nBase + row) * 640 + k0 + kq);
            va.x = tf32r(va.x); va.y = tf32r(va.y); va.z = tf32r(va.z); va.w = tf32r(va.w);
            vb.x = tf32r(vb.x); vb.y = tf32r(vb.y); vb.z = tf32r(vb.z); vb.w = tf32r(vb.w);
            *(float4*)&As[row][kq] = va;
            *(float4*)&Bs[row][kq] = vb;
        }
        __syncthreads();
#pragma unroll
        for (int ks = 0; ks < 4; ks++) {
            unsigned af[4][4], bf[4][2];
            const int ar = wm * 64 + (lane >> 2);
            const int ac = ks * 8 + (lane & 3);
#pragma unroll
            for (int mt = 0; mt < 4; mt++) {
                af[mt][0] = __float_as_uint(As[ar + mt * 16][ac]);
                af[mt][1] = __float_as_uint(As[ar + mt * 16 + 8][ac]);
                af[mt][2] = __float_as_uint(As[ar + mt * 16][ac + 4]);
                af[mt][3] = __float_as_uint(As[ar + mt * 16 + 8][ac + 4]);
            }
            const int br = wn * 32 + (lane >> 2);
#pragma unroll
            for (int nt = 0; nt < 4; nt++) {
                bf[nt][0] = __float_as_uint(Bs[br + nt * 8][ac]);
                bf[nt][1] = __float_as_uint(Bs[br + nt * 8][ac + 4]);
            }
#pragma unroll
            for (int mt = 0; mt < 4; mt++)
#pragma unroll
                for (int nt = 0; nt < 4; nt++)
                    asm volatile(
                        "mma.sync.aligned.m16n8k8.row.col.f32.tf32.tf32.f32 "
                        "{%0,%1,%2,%3},{%4,%5,%6,%7},{%8,%9},{%0,%1,%2,%3};\n"
                        : "+f"(acc[mt][nt][0]), "+f"(acc[mt][nt][1]),
                          "+f"(acc[mt][nt][2]), "+f"(acc[mt][nt][3])
                        : "r"(af[mt][0]), "r"(af[mt][1]), "r"(af[mt][2]), "r"(af[mt][3]),
                          "r"(bf[nt][0]), "r"(bf[nt][1]));
        }
        __syncthreads();
    }

#pragma unroll
    for (int mt = 0; mt < 4; mt++)
#pragma unroll
        for (int half = 0; half < 2; half++) {
            int gRow = mBase + wm * 64 + mt * 16 + (lane >> 2) + half * 8;
            float* op = g_pre1 + (size_t)gRow * G1 + nBase + wn * 32 + (lane & 3) * 2;
#pragma unroll
            for (int nt = 0; nt < 4; nt++) {
                float2 v;
                v.x = acc[mt][nt][half * 2 + 0];
                v.y = acc[mt][nt][half * 2 + 1];
                *reinterpret_cast<float2*>(op + nt * 8) = v;
            }
        }
}

// ---------------- persistent decode kernel ----------------
// smem layout (floats)
#define OFF_WS1  0
#define WS_STR   644
#define OFF_WS2  (16 * WS_STR)                 // 10304
#define OFF_US   (2 * 16 * WS_STR)             // 20608
#define OFF_GS   (OFF_US + 8192)               // 28800
#define OFF_GS2  (OFF_GS + 64 * 17)            // 29888
#define OFF_ES   (OFF_GS2 + 16 * 17)           // 30160
#define OFF_H2S  (OFF_ES + 512)                // 30672
#define OFF_RED  (OFF_H2S + 128)               // 30800
#define OFF_CTXS (OFF_RED + 64)                // 30864
#define SMEM_FLOATS (OFF_CTXS + 256)           // 31120
#define SMEM_BYTES  (SMEM_FLOATS * 4)

__global__ __launch_bounds__(256, 1) void decode_kernel(
    const float* __restrict__ enc_key, const float* __restrict__ values,
    const int* __restrict__ lens,
    const float* __restrict__ Wih1, const float* __restrict__ Whh1,
    const float* __restrict__ Wih2, const float* __restrict__ Whh2,
    float* __restrict__ attn_out)
{
    extern __shared__ float sm[];
    const int bi = blockIdx.x;
    const int tid = threadIdx.x;
    const int lane = tid & 31;
    const int wrp = tid >> 5;

    // ---- phase-A role constants: block owns d in [d0, d0+4) of h1 ----
    const int d0 = bi * 4;
    const int cidx = tid & 15;          // col within 16-col slice: gate*4+dl
    const int ngrp = tid >> 4;          // 16 batch groups of 4
    const int gateA = cidx >> 2, dlA = cidx & 3;
    const int gcol = gateA * HD + d0 + dlA;

    // ---- phase-B role constants: block owns 4 d2 x 16 batches ----
    const int d2base = (bi >> 2) * 4;
    const int nq = bi & 3;
    const int g2col = (cidx >> 2) * KSZ + d2base + (cidx & 3);
    const int nB0 = nq * 16;

    // load weight slices into smem (once)
    for (int i = tid; i < 16 * KREC; i += 256) {
        int c = i / KREC, k = i % KREC;
        int g = (c >> 2) * HD + d0 + (c & 3);
        float w = (k < VSZ) ? Wih1[(size_t)g * (HD + VSZ) + HD + k]
                            : Whh1[(size_t)g * HD + (k - VSZ)];
        sm[OFF_WS1 + c * WS_STR + k] = w;
    }
    for (int i = tid; i < 16 * KREC; i += 256) {
        int c = i / KREC, k = i % KREC;
        int g = (c >> 2) * KSZ + d2base + (c & 3);
        float w = (k < HD) ? Wih2[(size_t)g * HD + k]
                           : Whh2[(size_t)g * KSZ + (k - HD)];
        sm[OFF_WS2 + c * WS_STR + k] = w;
    }
    __syncthreads();

    const float bias1 = g_b1[gcol];
    const float bias2 = g_b2[g2col];
    const int len = (bi < NB) ? lens[bi] : 0;
    const int kk_fix = tid & 63;
    float* US = sm + OFF_US;
    int gen = 0;

    for (int t = 0; t < TD; t++) {
        // =============== PHASE A: gates1 + cell1 ===============
        {
            const float* h1r = g_h1[t & 1];
            float* h1w = g_h1[(t + 1) & 1];
            unsigned long long a0p = 0, a0q = 0, a1p = 0, a1q = 0;
            unsigned long long a2p = 0, a2q = 0, a3p = 0, a3q = 0;
            float pf[16];

            // prefetch tile 0
            {
                int k = kk_fix;
#pragma unroll
                for (int j = 0; j < 16; j++) {
                    int e = tid + j * 256, n = e >> 6;
                    pf[j] = (k < VSZ) ? g_ctx[n * VSZ + k] : h1r[n * HD + (k - VSZ)];
                }
#pragma unroll
                for (int j = 0; j < 16; j++) US[tid + j * 256] = pf[j];
            }
            __syncthreads();
            int buf = 0;
            for (int tile = 0; tile < 10; tile++) {
                if (tile < 9) {
                    int k = (tile + 1) * 64 + kk_fix;
#pragma unroll
                    for (int j = 0; j < 16; j++) {
                        int e = tid + j * 256, n = e >> 6;
                        pf[j] = (k < VSZ) ? g_ctx[n * VSZ + k] : h1r[n * HD + (k - VSZ)];
                    }
                }
                const float* W = sm + OFF_WS1 + cidx * WS_STR + tile * 64;
                const float* U = US + buf * 4096 + ngrp * 256;
#pragma unroll
                for (int kk = 0; kk < 64; kk += 4) {
                    ulonglong2 w  = *(const ulonglong2*)(W + kk);
                    ulonglong2 x0 = *(const ulonglong2*)(U + kk);
                    ulonglong2 x1 = *(const ulonglong2*)(U + 64 + kk);
                    ulonglong2 x2 = *(const ulonglong2*)(U + 128 + kk);
                    ulonglong2 x3 = *(const ulonglong2*)(U + 192 + kk);
                    FMA2(a0p, x0.x, w.x); FMA2(a0q, x0.y, w.y);
                    FMA2(a1p, x1.x, w.x); FMA2(a1q, x1.y, w.y);
                    FMA2(a2p, x2.x, w.x); FMA2(a2q, x2.y, w.y);
                    FMA2(a3p, x3.x, w.x); FMA2(a3q, x3.y, w.y);
                }
                if (tile < 9) {
                    float* D = US + (buf ^ 1) * 4096;
#pragma unroll
                    for (int j = 0; j < 16; j++) D[tid + j * 256] = pf[j];
                    __syncthreads();
                    buf ^= 1;
                }
            }
            float a0 = (f2lo(a0p) + f2hi(a0p)) + (f2lo(a0q) + f2hi(a0q));
            float a1 = (f2lo(a1p) + f2hi(a1p)) + (f2lo(a1q) + f2hi(a1q));
            float a2 = (f2lo(a2p) + f2hi(a2p)) + (f2lo(a2q) + f2hi(a2q));
            float a3 = (f2lo(a3p) + f2hi(a3p)) + (f2lo(a3q) + f2hi(a3q));
            // assemble pre-activations, exchange, cell update
            float* GS = sm + OFF_GS;
            {
                const float* pr = g_pre1 + (size_t)(t * NB) * G1 + gcol;
                int n0 = ngrp * 4;
                GS[(n0 + 0) * 17 + cidx] = a0 + __ldg(pr + (size_t)(n0 + 0) * G1) + bias1;
                GS[(n0 + 1) * 17 + cidx] = a1 + __ldg(pr + (size_t)(n0 + 1) * G1) + bias1;
                GS[(n0 + 2) * 17 + cidx] = a2 + __ldg(pr + (size_t)(n0 + 2) * G1) + bias1;
                GS[(n0 + 3) * 17 + cidx] = a3 + __ldg(pr + (size_t)(n0 + 3) * G1) + bias1;
            }
            __syncthreads();
            {
                int n = tid >> 2, dl = tid & 3;
                float gi = GS[n * 17 + 0 + dl];
                float gf = GS[n * 17 + 4 + dl];
                float gg = GS[n * 17 + 8 + dl];
                float go = GS[n * 17 + 12 + dl];
                int idx = n * HD + d0 + dl;
                float c = sigf(gf) * g_c1[idx] + sigf(gi) * tanhf(gg);
                g_c1[idx] = c;
                h1w[idx] = sigf(go) * tanhf(c);
            }
        }
        gbar(++gen);

        // =============== PHASE B: gates2 + cell2 ===============
        {
            const float* h1w = g_h1[(t + 1) & 1];
            const float* h2r = g_h2[t & 1];
            float* h2w = g_h2[(t + 1) & 1];
            unsigned long long ap2 = 0, aq2 = 0;
            float pf[4];
            {
                int k = kk_fix;
#pragma unroll
                for (int j = 0; j < 4; j++) {
                    int e = tid + j * 256, nn = e >> 6;
                    pf[j] = (k < HD) ? h1w[(nB0 + nn) * HD + k]
                                     : h2r[(nB0 + nn) * KSZ + (k - HD)];
                }
#pragma unroll
                for (int j = 0; j < 4; j++) US[tid + j * 256] = pf[j];
            }
            __syncthreads();
            int buf = 0;
            for (int tile = 0; tile < 10; tile++) {
                if (tile < 9) {
                    int k = (tile + 1) * 64 + kk_fix;
#pragma unroll
                    for (int j = 0; j < 4; j++) {
                        int e = tid + j * 256, nn = e >> 6;
                        pf[j] = (k < HD) ? h1w[(nB0 + nn) * HD + k]
                                         : h2r[(nB0 + nn) * KSZ + (k - HD)];
                    }
                }
                const float* W = sm + OFF_WS2 + cidx * WS_STR + tile * 64;
                const float* U = US + buf * 1024 + ngrp * 64;
#pragma unroll
                for (int kk = 0; kk < 64; kk += 4) {
                    ulonglong2 w = *(const ulonglong2*)(W + kk);
                    ulonglong2 x = *(const ulonglong2*)(U + kk);
                    FMA2(ap2, x.x, w.x);
                    FMA2(aq2, x.y, w.y);
                }
                if (tile < 9) {
                    float* D = US + (buf ^ 1) * 1024;
#pragma unroll
                    for (int j = 0; j < 4; j++) D[tid + j * 256] = pf[j];
                    __syncthreads();
                    buf ^= 1;
                }
            }
            float accv = (f2lo(ap2) + f2hi(ap2)) + (f2lo(aq2) + f2hi(aq2));
            float* GS2 = sm + OFF_GS2;
            GS2[ngrp * 17 + cidx] = accv + bias2;
            __syncthreads();
            if (tid < 64) {
                int ngl = tid >> 2, dl = tid & 3;
                int n = nB0 + ngl;
                float gi = GS2[ngl * 17 + 0 + dl];
                float gf = GS2[ngl * 17 + 4 + dl];
                float gg = GS2[ngl * 17 + 8 + dl];
                float go = GS2[ngl * 17 + 12 + dl];
                int idx = n * KSZ + d2base + dl;
                float c = sigf(gf) * g_c2[idx] + sigf(gi) * tanhf(gg);
                g_c2[idx] = c;
                float h = sigf(go) * tanhf(c);
                h2w[idx] = h;
                g_A[(size_t)(t * NB + n) * 256 + d2base + dl] = h;
            }
        }
        gbar(++gen);

        // =============== PHASE C: attention (64 blocks, one n each) ===============
        if (bi < NB) {
            const int n = bi;
            const float* h2w = g_h2[(t + 1) & 1];
            float* es = sm + OFF_ES;
            float* red = sm + OFF_RED;
            if (tid < KSZ) sm[OFF_H2S + tid] = h2w[n * KSZ + tid];
            __syncthreads();

            const float* ekn = enc_key + (size_t)n * TE * KSZ;
            const float4* h2s4 = (const float4*)(sm + OFF_H2S);
#pragma unroll
            for (int pass = 0; pass < 2; pass++) {
                int s = tid + pass * 256;
                const float4* row = (const float4*)(ekn + (size_t)s * KSZ);
                float e0 = 0.f, e1 = 0.f;
#pragma unroll 8
                for (int q = 0; q < 32; q += 2) {
                    float4 kv = row[q], hv = h2s4[q];
                    e0 += kv.x * hv.x + kv.y * hv.y + kv.z * hv.z + kv.w * hv.w;
                    float4 kv2 = row[q + 1], hv2 = h2s4[q + 1];
                    e1 += kv2.x * hv2.x + kv2.y * hv2.y + kv2.z * hv2.z + kv2.w * hv2.w;
                }
                es[s] = e0 + e1;
            }
            __syncthreads();

            float m = fmaxf(es[tid], es[tid + 256]);
#pragma unroll
            for (int o = 16; o; o >>= 1) m = fmaxf(m, __shfl_xor_sync(0xffffffffu, m, o));
            if (lane == 0) red[wrp] = m;
            __syncthreads();
            if (tid == 0) {
                float mm = red[0];
                for (int i = 1; i < 8; i++) mm = fmaxf(mm, red[i]);
                red[32] = mm;
            }
            __syncthreads();
            m = red[32];
            float p0 = (tid < len) ? expf(es[tid] - m) : 0.f;
            float p1 = (tid + 256 < len) ? expf(es[tid + 256] - m) : 0.f;
            float ssum = p0 + p1;
#pragma unroll
            for (int o = 16; o; o >>= 1) ssum += __shfl_xor_sync(0xffffffffu, ssum, o);
            if (lane == 0) red[wrp] = ssum;
            __syncthreads();
            if (tid == 0) {
                float ss = 0.f;
                for (int i = 0; i < 8; i++) ss += red[i];
                red[33] = ss;
            }
            __syncthreads();
            const float inv = 1.f / red[33];
            const float a0v = p0 * inv, a1v = p1 * inv;
            float* ao = attn_out + ((size_t)n * TD + t) * TE;
            __stcs(ao + tid, a0v);
            __stcs(ao + tid + 256, a1v);
            es[tid] = a0v;
            es[tid + 256] = a1v;
            __syncthreads();

            {
                int k = tid & 127, sh = tid >> 7;
                const float* vv = values + ((size_t)n * TE + sh * 256) * VSZ + k;
                const float* ap = es + sh * 256;
                float ac0 = 0.f, ac1 = 0.f, ac2 = 0.f, ac3 = 0.f;
#pragma unroll 8
                for (int s = 0; s < 256; s += 4) {
                    ac0 = fmaf(ap[s + 0], __ldg(vv + (size_t)(s + 0) * VSZ), ac0);
                    ac1 = fmaf(ap[s + 1], __ldg(vv + (size_t)(s + 1) * VSZ), ac1);
                    ac2 = fmaf(ap[s + 2], __ldg(vv + (size_t)(s + 2) * VSZ), ac2);
                    ac3 = fmaf(ap[s + 3], __ldg(vv + (size_t)(s + 3) * VSZ), ac3);
                }
                sm[OFF_CTXS + sh * 128 + k] = (ac0 + ac1) + (ac2 + ac3);
            }
            __syncthreads();
            if (tid < VSZ) {
                float cv = sm[OFF_CTXS + tid] + sm[OFF_CTXS + 128 + tid];
                g_ctx[n * VSZ + tid] = cv;
                g_A[(size_t)(t * NB + n) * 256 + KSZ + tid] = cv;
            }
        }
        if (t < TD - 1) gbar(++gen);   // final barrier elided: kernel boundary syncs
    }
}

// ---------------- final logits GEMM: out = A[6336,256] @ Wout^T + bout (tf32) -----
__global__ __launch_bounds__(256) void out_gemm(const float* __restrict__ B,
                                                const float* __restrict__ bout,
                                                float* __restrict__ out)
{
    __shared__ float As[128][36];
    __shared__ float Bs[128][36];
    const int tid = threadIdx.x;
    const int lane = tid & 31;
    const int warp = tid >> 5;
    const int wm = warp & 1;
    const int wn = warp >> 1;
    const int mBase = blockIdx.y * 128;
    const int nBase = blockIdx.x * 128;

    float acc[4][4][4];
#pragma unroll
    for (int i = 0; i < 4; i++)
#pragma unroll
        for (int j = 0; j < 4; j++)
#pragma unroll
            for (int q = 0; q < 4; q++) acc[i][j][q] = 0.f;

    const int lr = tid >> 3;
    const int kq = (tid & 7) * 4;

    for (int k0 = 0; k0 < 256; k0 += 32) {
#pragma unroll
        for (int p = 0; p < 4; p++) {
            int row = lr + p * 32;
            float4 va = *(const float4*)(g_A + (size_t)(mBase + row) * 256 + k0 + kq);
            float4 vb = *(const float4*)(B + (size_t)(nBase + row) * 256 + k0 + kq);
            va.x = tf32r(va.x); va.y = tf32r(va.y); va.z = tf32r(va.z); va.w = tf32r(va.w);
            vb.x = tf32r(vb.x); vb.y = tf32r(vb.y); vb.z = tf32r(vb.z); vb.w = tf32r(vb.w);
            *(float4*)&As[row][kq] = va;
            *(float4*)&Bs[row][kq] = vb;
        }
        __syncthreads();
#pragma unroll
        for (int ks = 0; ks < 4; ks++) {
            unsigned af[4][4], bf[4][2];
            const int ar = wm * 64 + (lane >> 2);
            const int ac = ks * 8 + (lane & 3);
#pragma unroll
            for (int mt = 0; mt < 4; mt++) {
                af[mt][0] = __float_as_uint(As[ar + mt * 16][ac]);
                af[mt][1] = __float_as_uint(As[ar + mt * 16 + 8][ac]);
                af[mt][2] = __float_as_uint(As[ar + mt * 16][ac + 4]);
                af[mt][3] = __float_as_uint(As[ar + mt * 16 + 8][ac + 4]);
            }
            const int br = wn * 32 + (lane >> 2);
#pragma unroll
            for (int nt = 0; nt < 4; nt++) {
                bf[nt][0] = __float_as_uint(Bs[br + nt * 8][ac]);
                bf[nt][1] = __float_as_uint(Bs[br + nt * 8][ac + 4]);
            }
#pragma unroll
            for (int mt = 0; mt < 4; mt++)
#pragma unroll
                for (int nt = 0; nt < 4; nt++)
                    asm volatile(
                        "mma.sync.aligned.m16n8k8.row.col.f32.tf32.tf32.f32 "
                        "{%0,%1,%2,%3},{%4,%5,%6,%7},{%8,%9},{%0,%1,%2,%3};\n"
                        : "+f"(acc[mt][nt][0]), "+f"(acc[mt][nt][1]),
                          "+f"(acc[mt][nt][2]), "+f"(acc[mt][nt][3])
                        : "r"(af[mt][0]), "r"(af[mt][1]), "r"(af[mt][2]), "r"(af[mt][3]),
                          "r"(bf[nt][0]), "r"(bf[nt][1]));
        }
        __syncthreads();
    }

#pragma unroll
    for (int mt = 0; mt < 4; mt++) {
#pragma unroll
        for (int half = 0; half < 2; half++) {
            int gRow = mBase + wm * 64 + mt * 16 + (lane >> 2) + half * 8;
            if (gRow < MROWS) {
                int outRow = (gRow & 63) * TD + (gRow >> 6);
                float* op = out + (size_t)outRow * VOC + nBase + wn * 32 + (lane & 3) * 2;
#pragma unroll
                for (int nt = 0; nt < 4; nt++) {
                    int bc = nBase + wn * 32 + nt * 8 + (lane & 3) * 2;
                    float2 v;
                    v.x = acc[mt][nt][half * 2 + 0] + bout[bc];
                    v.y = acc[mt][nt][half * 2 + 1] + bout[bc + 1];
                    __stcs(reinterpret_cast<float2*>(op + nt * 8), v);
                }
            }
        }
    }
}

// ---------------- launch ----------------
extern "C" void kernel_launch(void* const* d_in, const int* in_sizes, int n_in,
                              void* d_out, int out_size)
{
    const float* enc_key   = (const float*)d_in[0];
    const float* values    = (const float*)d_in[1];
    const int*   lens      = (const int*)d_in[2];
    const int*   text      = (const int*)d_in[3];
    const float* embedding = (const float*)d_in[4];
    const float* Wih1 = (const float*)d_in[5];
    const float* Whh1 = (const float*)d_in[6];
    const float* bih1 = (const float*)d_in[7];
    const float* bhh1 = (const float*)d_in[8];
    const float* Wih2 = (const float*)d_in[9];
    const float* Whh2 = (const float*)d_in[10];
    const float* bih2 = (const float*)d_in[11];
    const float* bhh2 = (const float*)d_in[12];
    const float* Wout = (const float*)d_in[13];
    const float* bout = (const float*)d_in[14];

    float* out = (float*)d_out;
    float* attn_out = out + (size_t)MROWS * VOC;

    cudaFuncSetAttribute((const void*)decode_kernel,
                         cudaFuncAttributeMaxDynamicSharedMemorySize, SMEM_BYTES);

    setup_kernel<<<2048, 256>>>(bih1, bhh1, bih2, bhh2, embedding, text);
    pre_gemm<<<dim3(G1 / 128, MPAD / 128), 256>>>(Wih1);
    decode_kernel<<<NBLK, 256, SMEM_BYTES>>>(enc_key, values, lens,
                                             Wih1, Whh1, Wih2, Whh2, attn_out);
    out_gemm<<<dim3(VOC / 128, MPAD / 128), 256>>>(Wout, bout, out);
}

// round 13
// speedup vs baseline: 1.2465x; 1.2465x over previous
#include <cuda_runtime.h>
#include <math.h>

#define NB   64
#define TE   512
#define KSZ  128
#define VSZ  128
#define HD   512
#define TD   99
#define VOC  32000
#define MROWS 6336
#define MPAD  6400
#define NBLK  128
#define G1   2048
#define G2   512
#define KREC 640            // serial K for both gate GEMMs

// ---------------- static device scratch ----------------
__device__ float g_embs[(size_t)MPAD * HD];          // 13.1 MB
__device__ float g_pre1[(size_t)MPAD * G1];          // 52.4 MB (emb part of gates1)
__device__ float g_A[(size_t)MPAD * 256];            // [t*64+n][h2|ctx]
__device__ float g_h1[2][NB * HD];
__device__ float g_c1[NB * HD];
__device__ float g_h2[2][NB * KSZ];
__device__ float g_c2[NB * KSZ];
__device__ float g_ctx[NB * VSZ];
__device__ float g_b1[G1];
__device__ float g_b2[G2];
__device__ int g_bar_cnt = 0;
__device__ volatile int g_bar_gen = 0;

__device__ __forceinline__ float sigf(float x) { return 1.f / (1.f + expf(-x)); }

__device__ __forceinline__ float tf32r(float x) {
    asm("cvt.rna.tf32.f32 %0, %0;" : "+f"(x));
    return x;
}

// packed dual-fp32 FMA (sm_100+)
#define FMA2(d, a, b) asm("fma.rn.f32x2 %0, %1, %2, %0;" : "+l"(d) : "l"(a), "l"(b))

__device__ __forceinline__ float f2lo(unsigned long long u) {
    return __uint_as_float((unsigned)u);
}
__device__ __forceinline__ float f2hi(unsigned long long u) {
    return __uint_as_float((unsigned)(u >> 32));
}

// grid-wide barrier: atomic counter, single poller per block (R7-proven shape).
// Generation counting is relative, so CUDA-graph replays are safe.
__device__ __forceinline__ void gbar() {
    __syncthreads();
    if (threadIdx.x == 0) {
        int gen = g_bar_gen;
        __threadfence();
        if (atomicAdd(&g_bar_cnt, 1) == NBLK - 1) {
            g_bar_cnt = 0;
            __threadfence();
            g_bar_gen = gen + 1;
        } else {
            while (g_bar_gen == gen) { }
            __threadfence();
        }
    }
    __syncthreads();
}

// ---------------- setup: states, biases, embedding gather ----------------
__global__ void setup_kernel(const float* __restrict__ bih1, const float* __restrict__ bhh1,
                             const float* __restrict__ bih2, const float* __restrict__ bhh2,
                             const float* __restrict__ embedding, const int* __restrict__ text)
{
    const long S_B1 = G1, S_B2 = G2;
    const long S_H1 = 2L * NB * HD, S_C1 = NB * HD;
    const long S_H2 = 2L * NB * KSZ, S_C2 = NB * KSZ, S_CTX = NB * VSZ;
    const long S_EMB = (long)MPAD * HD;
    const long S_APAD = (long)(MPAD - MROWS) * 256;
    const long total = S_B1 + S_B2 + S_H1 + S_C1 + S_H2 + S_C2 + S_CTX + S_EMB + S_APAD;
    const long stride = (long)gridDim.x * blockDim.x;

    for (long idx = (long)blockIdx.x * blockDim.x + threadIdx.x; idx < total; idx += stride) {
        long i = idx;
        if (i < S_B1) { g_b1[i] = bih1[i] + bhh1[i]; continue; } i -= S_B1;
        if (i < S_B2) { g_b2[i] = bih2[i] + bhh2[i]; continue; } i -= S_B2;
        if (i < S_H1) { ((float*)g_h1)[i] = 0.f; continue; } i -= S_H1;
        if (i < S_C1) { g_c1[i] = 0.f; continue; } i -= S_C1;
        if (i < S_H2) { ((float*)g_h2)[i] = 0.f; continue; } i -= S_H2;
        if (i < S_C2) { g_c2[i] = 0.f; continue; } i -= S_C2;
        if (i < S_CTX){ g_ctx[i] = 0.f; continue; } i -= S_CTX;
        if (i < S_EMB) {
            long row = i / HD; int d = (int)(i % HD);
            if (row < MROWS) {
                int t = (int)(row >> 6), n = (int)(row & 63);
                int tok = text[n * 100 + t];
                g_embs[i] = embedding[(size_t)tok * HD + d];
            } else g_embs[i] = 0.f;
            continue;
        }
        i -= S_EMB;
        g_A[(size_t)MROWS * 256 + i] = 0.f;
    }
}

// ---------------- tf32 GEMM: g_pre1[6400,2048] = g_embs[6400,512] @ Wih1[:, :512]^T --
__global__ __launch_bounds__(256) void pre_gemm(const float* __restrict__ B)
{
    __shared__ float As[128][36];
    __shared__ float Bs[128][36];
    const int tid = threadIdx.x;
    const int lane = tid & 31;
    const int warp = tid >> 5;
    const int wm = warp & 1;
    const int wn = warp >> 1;
    const int mBase = blockIdx.y * 128;
    const int nBase = blockIdx.x * 128;

    float acc[4][4][4];
#pragma unroll
    for (int i = 0; i < 4; i++)
#pragma unroll
        for (int j = 0; j < 4; j++)
#pragma unroll
            for (int q = 0; q < 4; q++) acc[i][j][q] = 0.f;

    const int lr = tid >> 3;
    const int kq = (tid & 7) * 4;

    for (int k0 = 0; k0 < 512; k0 += 32) {
#pragma unroll
        for (int p = 0; p < 4; p++) {
            int row = lr + p * 32;
            float4 va = *(const float4*)(g_embs + (size_t)(mBase + row) * 512 + k0 + kq);
            float4 vb = *(const float4*)(B + (size_t)(nBase + row) * 640 + k0 + kq);
            va.x = tf32r(va.x); va.y = tf32r(va.y); va.z = tf32r(va.z); va.w = tf32r(va.w);
            vb.x = tf32r(vb.x); vb.y = tf32r(vb.y); vb.z = tf32r(vb.z); vb.w = tf32r(vb.w);
            *(float4*)&As[row][kq] = va;
            *(float4*)&Bs[row][kq] = vb;
        }
        __syncthreads();
#pragma unroll
        for (int ks = 0; ks < 4; ks++) {
            unsigned af[4][4], bf[4][2];
            const int ar = wm * 64 + (lane >> 2);
            const int ac = ks * 8 + (lane & 3);
#pragma unroll
            for (int mt = 0; mt < 4; mt++) {
                af[mt][0] = __float_as_uint(As[ar + mt * 16][ac]);
                af[mt][1] = __float_as_uint(As[ar + mt * 16 + 8][ac]);
                af[mt][2] = __float_as_uint(As[ar + mt * 16][ac + 4]);
                af[mt][3] = __float_as_uint(As[ar + mt * 16 + 8][ac + 4]);
            }
            const int br = wn * 32 + (lane >> 2);
#pragma unroll
            for (int nt = 0; nt < 4; nt++) {
                bf[nt][0] = __float_as_uint(Bs[br + nt * 8][ac]);
                bf[nt][1] = __float_as_uint(Bs[br + nt * 8][ac + 4]);
            }
#pragma unroll
            for (int mt = 0; mt < 4; mt++)
#pragma unroll
                for (int nt = 0; nt < 4; nt++)
                    asm volatile(
                        "mma.sync.aligned.m16n8k8.row.col.f32.tf32.tf32.f32 "
                        "{%0,%1,%2,%3},{%4,%5,%6,%7},{%8,%9},{%0,%1,%2,%3};\n"
                        : "+f"(acc[mt][nt][0]), "+f"(acc[mt][nt][1]),
                          "+f"(acc[mt][nt][2]), "+f"(acc[mt][nt][3])
                        : "r"(af[mt][0]), "r"(af[mt][1]), "r"(af[mt][2]), "r"(af[mt][3]),
                          "r"(bf[nt][0]), "r"(bf[nt][1]));
        }
        __syncthreads();
    }

#pragma unroll
    for (int mt = 0; mt < 4; mt++)
#pragma unroll
        for (int half = 0; half < 2; half++) {
            int gRow = mBase + wm * 64 + mt * 16 + (lane >> 2) + half * 8;
            float* op = g_pre1 + (size_t)gRow * G1 + nBase + wn * 32 + (lane & 3) * 2;
#pragma unroll
            for (int nt = 0; nt < 4; nt++) {
                float2 v;
                v.x = acc[mt][nt][half * 2 + 0];
                v.y = acc[mt][nt][half * 2 + 1];
                *reinterpret_cast<float2*>(op + nt * 8) = v;
            }
        }
}

// ---------------- persistent decode kernel ----------------
// smem layout (floats)
#define OFF_WS1  0
#define WS_STR   644
#define OFF_WS2  (16 * WS_STR)                 // 10304
#define OFF_US   (2 * 16 * WS_STR)             // 20608
#define OFF_GS   (OFF_US + 8192)               // 28800
#define OFF_GS2  (OFF_GS + 64 * 17)            // 29888
#define OFF_ES   (OFF_GS2 + 16 * 17)           // 30160
#define OFF_H2S  (OFF_ES + 512)                // 30672
#define OFF_RED  (OFF_H2S + 128)               // 30800
#define OFF_CTXS (OFF_RED + 64)                // 30864
#define SMEM_FLOATS (OFF_CTXS + 256)           // 31120
#define SMEM_BYTES  (SMEM_FLOATS * 4)

__global__ __launch_bounds__(256, 1) void decode_kernel(
    const float* __restrict__ enc_key, const float* __restrict__ values,
    const int* __restrict__ lens,
    const float* __restrict__ Wih1, const float* __restrict__ Whh1,
    const float* __restrict__ Wih2, const float* __restrict__ Whh2,
    float* __restrict__ attn_out)
{
    extern __shared__ float sm[];
    const int bi = blockIdx.x;
    const int tid = threadIdx.x;
    const int lane = tid & 31;
    const int wrp = tid >> 5;

    // ---- phase-A role constants: block owns d in [d0, d0+4) of h1 ----
    const int d0 = bi * 4;
    const int cidx = tid & 15;          // col within 16-col slice: gate*4+dl
    const int ngrp = tid >> 4;          // 16 batch groups of 4
    const int gateA = cidx >> 2, dlA = cidx & 3;
    const int gcol = gateA * HD + d0 + dlA;

    // ---- phase-B role constants: block owns 4 d2 x 16 batches ----
    const int d2base = (bi >> 2) * 4;
    const int nq = bi & 3;
    const int g2col = (cidx >> 2) * KSZ + d2base + (cidx & 3);
    const int nB0 = nq * 16;

    // load weight slices into smem (once)
    for (int i = tid; i < 16 * KREC; i += 256) {
        int c = i / KREC, k = i % KREC;
        int g = (c >> 2) * HD + d0 + (c & 3);
        float w = (k < VSZ) ? Wih1[(size_t)g * (HD + VSZ) + HD + k]
                            : Whh1[(size_t)g * HD + (k - VSZ)];
        sm[OFF_WS1 + c * WS_STR + k] = w;
    }
    for (int i = tid; i < 16 * KREC; i += 256) {
        int c = i / KREC, k = i % KREC;
        int g = (c >> 2) * KSZ + d2base + (c & 3);
        float w = (k < HD) ? Wih2[(size_t)g * HD + k]
                           : Whh2[(size_t)g * KSZ + (k - HD)];
        sm[OFF_WS2 + c * WS_STR + k] = w;
    }
    __syncthreads();

    const float bias1 = g_b1[gcol];
    const float bias2 = g_b2[g2col];
    const int len = (bi < NB) ? lens[bi] : 0;
    const int kk_fix = tid & 63;
    float* US = sm + OFF_US;

    for (int t = 0; t < TD; t++) {
        // =============== PHASE A: gates1 + cell1 ===============
        {
            const float* h1r = g_h1[t & 1];
            float* h1w = g_h1[(t + 1) & 1];
            unsigned long long a0p = 0, a0q = 0, a1p = 0, a1q = 0;
            unsigned long long a2p = 0, a2q = 0, a3p = 0, a3q = 0;
            float pf[16];

            // hoisted g_pre1 loads (DRAM-cold): issue early, consume at the end
            const float* pr = g_pre1 + (size_t)(t * NB) * G1 + gcol;
            const int n0 = ngrp * 4;
            const float pr0 = __ldg(pr + (size_t)(n0 + 0) * G1);
            const float pr1 = __ldg(pr + (size_t)(n0 + 1) * G1);
            const float pr2 = __ldg(pr + (size_t)(n0 + 2) * G1);
            const float pr3 = __ldg(pr + (size_t)(n0 + 3) * G1);

            // prefetch tile 0
            {
                int k = kk_fix;
#pragma unroll
                for (int j = 0; j < 16; j++) {
                    int e = tid + j * 256, n = e >> 6;
                    pf[j] = (k < VSZ) ? g_ctx[n * VSZ + k] : h1r[n * HD + (k - VSZ)];
                }
#pragma unroll
                for (int j = 0; j < 16; j++) US[tid + j * 256] = pf[j];
            }
            __syncthreads();
            int buf = 0;
            for (int tile = 0; tile < 10; tile++) {
                if (tile < 9) {
                    int k = (tile + 1) * 64 + kk_fix;
#pragma unroll
                    for (int j = 0; j < 16; j++) {
                        int e = tid + j * 256, n = e >> 6;
                        pf[j] = (k < VSZ) ? g_ctx[n * VSZ + k] : h1r[n * HD + (k - VSZ)];
                    }
                }
                const float* W = sm + OFF_WS1 + cidx * WS_STR + tile * 64;
                const float* U = US + buf * 4096 + ngrp * 256;
#pragma unroll
                for (int kk = 0; kk < 64; kk += 4) {
                    ulonglong2 w  = *(const ulonglong2*)(W + kk);
                    ulonglong2 x0 = *(const ulonglong2*)(U + kk);
                    ulonglong2 x1 = *(const ulonglong2*)(U + 64 + kk);
                    ulonglong2 x2 = *(const ulonglong2*)(U + 128 + kk);
                    ulonglong2 x3 = *(const ulonglong2*)(U + 192 + kk);
                    FMA2(a0p, x0.x, w.x); FMA2(a0q, x0.y, w.y);
                    FMA2(a1p, x1.x, w.x); FMA2(a1q, x1.y, w.y);
                    FMA2(a2p, x2.x, w.x); FMA2(a2q, x2.y, w.y);
                    FMA2(a3p, x3.x, w.x); FMA2(a3q, x3.y, w.y);
                }
                if (tile < 9) {
                    float* D = US + (buf ^ 1) * 4096;
#pragma unroll
                    for (int j = 0; j < 16; j++) D[tid + j * 256] = pf[j];
                    __syncthreads();
                    buf ^= 1;
                }
            }
            float a0 = (f2lo(a0p) + f2hi(a0p)) + (f2lo(a0q) + f2hi(a0q));
            float a1 = (f2lo(a1p) + f2hi(a1p)) + (f2lo(a1q) + f2hi(a1q));
            float a2 = (f2lo(a2p) + f2hi(a2p)) + (f2lo(a2q) + f2hi(a2q));
            float a3 = (f2lo(a3p) + f2hi(a3p)) + (f2lo(a3q) + f2hi(a3q));
            // assemble pre-activations, exchange, cell update
            float* GS = sm + OFF_GS;
            {
                GS[(n0 + 0) * 17 + cidx] = a0 + pr0 + bias1;
                GS[(n0 + 1) * 17 + cidx] = a1 + pr1 + bias1;
                GS[(n0 + 2) * 17 + cidx] = a2 + pr2 + bias1;
                GS[(n0 + 3) * 17 + cidx] = a3 + pr3 + bias1;
            }
            __syncthreads();
            {
                int n = tid >> 2, dl = tid & 3;
                float gi = GS[n * 17 + 0 + dl];
                float gf = GS[n * 17 + 4 + dl];
                float gg = GS[n * 17 + 8 + dl];
                float go = GS[n * 17 + 12 + dl];
                int idx = n * HD + d0 + dl;
                float c = sigf(gf) * g_c1[idx] + sigf(gi) * tanhf(gg);
                g_c1[idx] = c;
                h1w[idx] = sigf(go) * tanhf(c);
            }
        }
        gbar();

        // =============== PHASE B: gates2 + cell2 ===============
        {
            const float* h1w = g_h1[(t + 1) & 1];
            const float* h2r = g_h2[t & 1];
            float* h2w = g_h2[(t + 1) & 1];
            unsigned long long ap2 = 0, aq2 = 0;
            float pf[4];
            {
                int k = kk_fix;
#pragma unroll
                for (int j = 0; j < 4; j++) {
                    int e = tid + j * 256, nn = e >> 6;
                    pf[j] = (k < HD) ? h1w[(nB0 + nn) * HD + k]
                                     : h2r[(nB0 + nn) * KSZ + (k - HD)];
                }
#pragma unroll
                for (int j = 0; j < 4; j++) US[tid + j * 256] = pf[j];
            }
            __syncthreads();
            int buf = 0;
            for (int tile = 0; tile < 10; tile++) {
                if (tile < 9) {
                    int k = (tile + 1) * 64 + kk_fix;
#pragma unroll
                    for (int j = 0; j < 4; j++) {
                        int e = tid + j * 256, nn = e >> 6;
                        pf[j] = (k < HD) ? h1w[(nB0 + nn) * HD + k]
                                         : h2r[(nB0 + nn) * KSZ + (k - HD)];
                    }
                }
                const float* W = sm + OFF_WS2 + cidx * WS_STR + tile * 64;
                const float* U = US + buf * 1024 + ngrp * 64;
#pragma unroll
                for (int kk = 0; kk < 64; kk += 4) {
                    ulonglong2 w = *(const ulonglong2*)(W + kk);
                    ulonglong2 x = *(const ulonglong2*)(U + kk);
                    FMA2(ap2, x.x, w.x);
                    FMA2(aq2, x.y, w.y);
                }
                if (tile < 9) {
                    float* D = US + (buf ^ 1) * 1024;
#pragma unroll
                    for (int j = 0; j < 4; j++) D[tid + j * 256] = pf[j];
                    __syncthreads();
                    buf ^= 1;
                }
            }
            float accv = (f2lo(ap2) + f2hi(ap2)) + (f2lo(aq2) + f2hi(aq2));
            float* GS2 = sm + OFF_GS2;
            GS2[ngrp * 17 + cidx] = accv + bias2;
            __syncthreads();
            if (tid < 64) {
                int ngl = tid >> 2, dl = tid & 3;
                int n = nB0 + ngl;
                float gi = GS2[ngl * 17 + 0 + dl];
                float gf = GS2[ngl * 17 + 4 + dl];
                float gg = GS2[ngl * 17 + 8 + dl];
                float go = GS2[ngl * 17 + 12 + dl];
                int idx = n * KSZ + d2base + dl;
                float c = sigf(gf) * g_c2[idx] + sigf(gi) * tanhf(gg);
                g_c2[idx] = c;
                float h = sigf(go) * tanhf(c);
                h2w[idx] = h;
                g_A[(size_t)(t * NB + n) * 256 + d2base + dl] = h;
            }
        }
        gbar();

        // =============== PHASE C: attention (64 blocks, one n each) ===============
        if (bi < NB) {
            const int n = bi;
            const float* h2w = g_h2[(t + 1) & 1];
            float* es = sm + OFF_ES;
            float* red = sm + OFF_RED;
            if (tid < KSZ) sm[OFF_H2S + tid] = h2w[n * KSZ + tid];
            __syncthreads();

            const float* ekn = enc_key + (size_t)n * TE * KSZ;
            const float4* h2s4 = (const float4*)(sm + OFF_H2S);
#pragma unroll
            for (int pass = 0; pass < 2; pass++) {
                int s = tid + pass * 256;
                if (s < len) {
                    const float4* row = (const float4*)(ekn + (size_t)s * KSZ);
                    float e0 = 0.f, e1 = 0.f;
#pragma unroll 8
                    for (int q = 0; q < 32; q += 2) {
                        float4 kv = row[q], hv = h2s4[q];
                        e0 += kv.x * hv.x + kv.y * hv.y + kv.z * hv.z + kv.w * hv.w;
                        float4 kv2 = row[q + 1], hv2 = h2s4[q + 1];
                        e1 += kv2.x * hv2.x + kv2.y * hv2.y + kv2.z * hv2.z + kv2.w * hv2.w;
                    }
                    es[s] = e0 + e1;
                } else {
                    es[s] = 0.f;
                }
            }
            __syncthreads();

            // max over es (includes zeros beyond len: harmless, shift cancels in renorm)
            float m = fmaxf(es[tid], es[tid + 256]);
#pragma unroll
            for (int o = 16; o; o >>= 1) m = fmaxf(m, __shfl_xor_sync(0xffffffffu, m, o));
            if (lane == 0) red[wrp] = m;
            __syncthreads();
            if (tid == 0) {
                float mm = red[0];
                for (int i = 1; i < 8; i++) mm = fmaxf(mm, red[i]);
                red[32] = mm;
            }
            __syncthreads();
            m = red[32];
            float p0 = (tid < len) ? expf(es[tid] - m) : 0.f;
            float p1 = (tid + 256 < len) ? expf(es[tid + 256] - m) : 0.f;
            float ssum = p0 + p1;
#pragma unroll
            for (int o = 16; o; o >>= 1) ssum += __shfl_xor_sync(0xffffffffu, ssum, o);
            if (lane == 0) red[wrp] = ssum;
            __syncthreads();
            if (tid == 0) {
                float ss = 0.f;
                for (int i = 0; i < 8; i++) ss += red[i];
                red[33] = ss;
            }
            __syncthreads();
            const float inv = 1.f / red[33];
            const float a0v = p0 * inv, a1v = p1 * inv;
            float* ao = attn_out + ((size_t)n * TD + t) * TE;
            __stcs(ao + tid, a0v);
            __stcs(ao + tid + 256, a1v);
            es[tid] = a0v;
            es[tid + 256] = a1v;
            __syncthreads();

            {
                int k = tid & 127, sh = tid >> 7;
                int lim = sh ? (len - 256) : 256;   // len >= 256 always
                const float* vv = values + ((size_t)n * TE + sh * 256) * VSZ + k;
                const float* ap = es + sh * 256;
                float ac0 = 0.f, ac1 = 0.f, ac2 = 0.f, ac3 = 0.f;
                int s4 = lim & ~3;
#pragma unroll 8
                for (int s = 0; s < s4; s += 4) {
                    ac0 = fmaf(ap[s + 0], __ldg(vv + (size_t)(s + 0) * VSZ), ac0);
                    ac1 = fmaf(ap[s + 1], __ldg(vv + (size_t)(s + 1) * VSZ), ac1);
                    ac2 = fmaf(ap[s + 2], __ldg(vv + (size_t)(s + 2) * VSZ), ac2);
                    ac3 = fmaf(ap[s + 3], __ldg(vv + (size_t)(s + 3) * VSZ), ac3);
                }
                for (int s = s4; s < lim; s++)
                    ac0 = fmaf(ap[s], __ldg(vv + (size_t)s * VSZ), ac0);
                sm[OFF_CTXS + sh * 128 + k] = (ac0 + ac1) + (ac2 + ac3);
            }
            __syncthreads();
            if (tid < VSZ) {
                float cv = sm[OFF_CTXS + tid] + sm[OFF_CTXS + 128 + tid];
                g_ctx[n * VSZ + tid] = cv;
                g_A[(size_t)(t * NB + n) * 256 + KSZ + tid] = cv;
            }
        }
        if (t < TD - 1) gbar();   // final barrier elided: kernel boundary syncs
    }
}

// ---------------- final logits GEMM: out = A[6336,256] @ Wout^T + bout (tf32) -----
__global__ __launch_bounds__(256) void out_gemm(const float* __restrict__ B,
                                                const float* __restrict__ bout,
                                                float* __restrict__ out)
{
    __shared__ float As[128][36];
    __shared__ float Bs[128][36];
    const int tid = threadIdx.x;
    const int lane = tid & 31;
    const int warp = tid >> 5;
    const int wm = warp & 1;
    const int wn = warp >> 1;
    const int mBase = blockIdx.y * 128;
    const int nBase = blockIdx.x * 128;

    float acc[4][4][4];
#pragma unroll
    for (int i = 0; i < 4; i++)
#pragma unroll
        for (int j = 0; j < 4; j++)
#pragma unroll
            for (int q = 0; q < 4; q++) acc[i][j][q] = 0.f;

    const int lr = tid >> 3;
    const int kq = (tid & 7) * 4;

    for (int k0 = 0; k0 < 256; k0 += 32) {
#pragma unroll
        for (int p = 0; p < 4; p++) {
            int row = lr + p * 32;
            float4 va = *(const float4*)(g_A + (size_t)(mBase + row) * 256 + k0 + kq);
            float4 vb = *(const float4*)(B + (size_t)(nBase + row) * 256 + k0 + kq);
            va.x = tf32r(va.x); va.y = tf32r(va.y); va.z = tf32r(va.z); va.w = tf32r(va.w);
            vb.x = tf32r(vb.x); vb.y = tf32r(vb.y); vb.z = tf32r(vb.z); vb.w = tf32r(vb.w);
            *(float4*)&As[row][kq] = va;
            *(float4*)&Bs[row][kq] = vb;
        }
        __syncthreads();
#pragma unroll
        for (int ks = 0; ks < 4; ks++) {
            unsigned af[4][4], bf[4][2];
            const int ar = wm * 64 + (lane >> 2);
            const int ac = ks * 8 + (lane & 3);
#pragma unroll
            for (int mt = 0; mt < 4; mt++) {
                af[mt][0] = __float_as_uint(As[ar + mt * 16][ac]);
                af[mt][1] = __float_as_uint(As[ar + mt * 16 + 8][ac]);
                af[mt][2] = __float_as_uint(As[ar + mt * 16][ac + 4]);
                af[mt][3] = __float_as_uint(As[ar + mt * 16 + 8][ac + 4]);
            }
            const int br = wn * 32 + (lane >> 2);
#pragma unroll
            for (int nt = 0; nt < 4; nt++) {
                bf[nt][0] = __float_as_uint(Bs[br + nt * 8][ac]);
                bf[nt][1] = __float_as_uint(Bs[br + nt * 8][ac + 4]);
            }
#pragma unroll
            for (int mt = 0; mt < 4; mt++)
#pragma unroll
                for (int nt = 0; nt < 4; nt++)
                    asm volatile(
                        "mma.sync.aligned.m16n8k8.row.col.f32.tf32.tf32.f32 "
                        "{%0,%1,%2,%3},{%4,%5,%6,%7},{%8,%9},{%0,%1,%2,%3};\n"
                        : "+f"(acc[mt][nt][0]), "+f"(acc[mt][nt][1]),
                          "+f"(acc[mt][nt][2]), "+f"(acc[mt][nt][3])
                        : "r"(af[mt][0]), "r"(af[mt][1]), "r"(af[mt][2]), "r"(af[mt][3]),
                          "r"(bf[nt][0]), "r"(bf[nt][1]));
        }
        __syncthreads();
    }

#pragma unroll
    for (int mt = 0; mt < 4; mt++) {
#pragma unroll
        for (int half = 0; half < 2; half++) {
            int gRow = mBase + wm * 64 + mt * 16 + (lane >> 2) + half * 8;
            if (gRow < MROWS) {
                int outRow = (gRow & 63) * TD + (gRow >> 6);
                float* op = out + (size_t)outRow * VOC + nBase + wn * 32 + (lane & 3) * 2;
#pragma unroll
                for (int nt = 0; nt < 4; nt++) {
                    int bc = nBase + wn * 32 + nt * 8 + (lane & 3) * 2;
                    float2 v;
                    v.x = acc[mt][nt][half * 2 + 0] + bout[bc];
                    v.y = acc[mt][nt][half * 2 + 1] + bout[bc + 1];
                    __stcs(reinterpret_cast<float2*>(op + nt * 8), v);
                }
            }
        }
    }
}

// ---------------- launch ----------------
extern "C" void kernel_launch(void* const* d_in, const int* in_sizes, int n_in,
                              void* d_out, int out_size)
{
    const float* enc_key   = (const float*)d_in[0];
    const float* values    = (const float*)d_in[1];
    const int*   lens      = (const int*)d_in[2];
    const int*   text      = (const int*)d_in[3];
    const float* embedding = (const float*)d_in[4];
    const float* Wih1 = (const float*)d_in[5];
    const float* Whh1 = (const float*)d_in[6];
    const float* bih1 = (const float*)d_in[7];
    const float* bhh1 = (const float*)d_in[8];
    const float* Wih2 = (const float*)d_in[9];
    const float* Whh2 = (const float*)d_in[10];
    const float* bih2 = (const float*)d_in[11];
    const float* bhh2 = (const float*)d_in[12];
    const float* Wout = (const float*)d_in[13];
    const float* bout = (const float*)d_in[14];

    float* out = (float*)d_out;
    float* attn_out = out + (size_t)MROWS * VOC;

    cudaFuncSetAttribute((const void*)decode_kernel,
                         cudaFuncAttributeMaxDynamicSharedMemorySize, SMEM_BYTES);

    setup_kernel<<<2048, 256>>>(bih1, bhh1, bih2, bhh2, embedding, text);
    pre_gemm<<<dim3(G1 / 128, MPAD / 128), 256>>>(Wih1);
    decode_kernel<<<NBLK, 256, SMEM_BYTES>>>(enc_key, values, lens,
                                             Wih1, Whh1, Wih2, Whh2, attn_out);
    out_gemm<<<dim3(VOC / 128, MPAD / 128), 256>>>(Wout, bout, out);
}